// round 16
// baseline (speedup 1.0000x reference)
#include <cuda_runtime.h>
#include <cstdint>

// nu_grid_sampler: out[b,c,n] = x[b,c,px,py], x:(8,128,256,256) f32,
// coords:(8,32768,2) f32, out:(8,128,32768) f32.
//
// R16 = R15's gather (line-sorted direct gather: near-coalesced LDG, STS into
// a 128KB smem out-plane, dense float4 flush; 76.7us measured) + the entire
// counting sort FUSED into one kernel (8 blocks, one per batch): smem hist ->
// smem scan -> atomic-cursor scatter. Replaces memset + hist + prefix +
// scatter (4 serialized launches, ~16us) with one ~6us launch. Within-bucket
// order is irrelevant (any unique slot), which is what makes the single-pass
// atomic scatter valid.

#define GS_B 8
#define GS_C 128
#define GS_NX 256
#define GS_NY 256
#define GS_N 32768
#define GS_PIX (GS_NX * GS_NY)     // 65536
#define NBUCK 2048                  // idx>>5 : one 128B line per bucket
#define K2_THREADS 1024
#define ITERS (GS_N / K2_THREADS)   // 32
#define OBUF_BYTES (GS_N * 4)       // 128KB

__device__ unsigned g_idx[GS_B * GS_N];      // raw pixel idx per point
__device__ unsigned g_sorted[GS_B * GS_N];   // idx | (j<<16), line-sorted

__device__ __forceinline__ unsigned compute_idx(float cy, float cx) {
    float pxf = fminf(fmaxf(cx * (float)(GS_NX - 1), 0.0f), (float)GS_NX);
    float pyf = fminf(fmaxf(cy * (float)(GS_NY - 1), 0.0f), (float)GS_NY);
    int idx = (int)pxf * GS_NY + (int)pyf;
    return (unsigned)min(idx, GS_PIX - 1);   // take_along_axis clamp
}

// One block per batch: hist -> scan -> scatter, all in smem.
__global__ __launch_bounds__(1024)
void sort_kernel(const float* __restrict__ coords) {
    __shared__ int hist[NBUCK];     // 8KB
    __shared__ int cursor[NBUCK];   // 8KB
    __shared__ int ps[1024];        // 4KB
    const int t = threadIdx.x;
    const int b = blockIdx.x;

    hist[t] = 0; hist[t + 1024] = 0;
    __syncthreads();

    // Pass 1: compute indices, histogram by line bucket.
    const float2* __restrict__ cb = reinterpret_cast<const float2*>(coords)
                                    + (size_t)b * GS_N;
    unsigned* __restrict__ gi = g_idx + b * GS_N;
    #pragma unroll
    for (int it = 0; it < ITERS; ++it) {
        int j = (it << 10) + t;
        float2 co = cb[j];
        unsigned idx = compute_idx(co.x, co.y);
        gi[j] = idx;
        atomicAdd(&hist[idx >> 5], 1);
    }
    __syncthreads();

    // Exclusive scan of 2048 buckets (pairwise + Hillis-Steele over 1024).
    int pairsum = hist[2 * t] + hist[2 * t + 1];
    ps[t] = pairsum;
    __syncthreads();
    for (int off = 1; off < 1024; off <<= 1) {
        int v = (t >= off) ? ps[t - off] : 0;
        __syncthreads();
        ps[t] += v;
        __syncthreads();
    }
    int base = ps[t] - pairsum;
    cursor[2 * t]     = base;
    cursor[2 * t + 1] = base + hist[2 * t];
    __syncthreads();

    // Pass 2: scatter entries to unique slots via atomic cursors.
    unsigned* __restrict__ gs = g_sorted + b * GS_N;
    #pragma unroll
    for (int it = 0; it < ITERS; ++it) {
        int j = (it << 10) + t;
        unsigned idx = gi[j];
        int r = atomicAdd(&cursor[idx >> 5], 1);
        gs[r] = idx | ((unsigned)j << 16);
    }
}

__global__ __launch_bounds__(K2_THREADS, 1)
void gather_kernel(const float* __restrict__ x, float* __restrict__ out) {
    extern __shared__ float obuf[];              // 32768 floats = 128KB
    const int tid = threadIdx.x;
    const int bc  = blockIdx.x;                  // b*128 + c
    const int b   = bc >> 7;

    const float* __restrict__ plane    = x + ((size_t)bc << 16);
    const unsigned* __restrict__ ents  = g_sorted + b * GS_N;

    // 32 iterations: coalesced entry load, near-coalesced sorted gather,
    // STS scatter into the smem out-plane.
    #pragma unroll 8
    for (int it = 0; it < ITERS; ++it) {
        unsigned e = __ldg(ents + (it << 10) + tid);
        obuf[e >> 16] = __ldg(plane + (e & 0xFFFFu));
    }
    __syncthreads();

    // Dense float4 flush: STG.128 retires asynchronously (no tail wait).
    float* __restrict__ ob = out + ((size_t)bc << 15);
    #pragma unroll
    for (int q = 0; q < GS_N / (K2_THREADS * 4); ++q) {   // 8 iters
        int o = (q * K2_THREADS + tid) * 4;
        float4 v = *reinterpret_cast<const float4*>(&obuf[o]);
        *reinterpret_cast<float4*>(&ob[o]) = v;
    }
}

extern "C" void kernel_launch(void* const* d_in, const int* in_sizes, int n_in,
                              void* d_out, int out_size) {
    const float* x      = (const float*)d_in[0];   // (8,128,256,256) f32
    const float* coords = (const float*)d_in[1];   // (8,32768,2) f32
    float* out          = (float*)d_out;           // (8,128,32768) f32

    static int smem_set = 0;
    if (!smem_set) {
        cudaFuncSetAttribute(gather_kernel,
                             cudaFuncAttributeMaxDynamicSharedMemorySize,
                             OBUF_BYTES);
        smem_set = 1;
    }

    sort_kernel<<<GS_B, 1024>>>(coords);
    gather_kernel<<<GS_B * GS_C, K2_THREADS, OBUF_BYTES>>>(x, out);
}